// round 3
// baseline (speedup 1.0000x reference)
#include <cuda_runtime.h>
#include <math.h>

#define BN 512
#define TD 2048
#define SD 768
#define HD 128

typedef unsigned long long ull;

// Scratch (device globals — no allocations allowed)
__device__ float g_tp[BN*HD];
__device__ float g_sp[BN*HD];
__device__ float g_Ut[BN*HD];
__device__ float g_Vt[BN*HD];
__device__ float g_Us[BN*HD];
__device__ float g_Vs[BN*HD];
// Partial pre-sigmoid dots: [net(2)][hsplit(4)][BN*BN]
__device__ float g_pd[8] [BN*BN/1] ;  // 8 MB

// ---- packed f32x2 helpers (sm_100+) --------------------------------------
__device__ __forceinline__ ull pk2(float a, float b) {
    ull r; asm("mov.b64 %0, {%1, %2};" : "=l"(r) : "f"(a), "f"(b)); return r;
}
__device__ __forceinline__ float2 unpk2(ull v) {
    float2 r; asm("mov.b64 {%0, %1}, %2;" : "=f"(r.x), "=f"(r.y) : "l"(v)); return r;
}
__device__ __forceinline__ void fma2(ull &acc, ull a, ull b) {
    asm("fma.rn.f32x2 %0, %1, %2, %0;" : "+l"(acc) : "l"(a), "l"(b));
}
// acc += relu(a + b) * w (packed 2xfp32)
__device__ __forceinline__ void rfma2(ull &acc, ull a, ull b, ull w) {
    asm("{\n\t"
        ".reg .b64 t;\n\t"
        ".reg .f32 tl, th;\n\t"
        "add.rn.f32x2 t, %1, %2;\n\t"
        "mov.b64 {tl, th}, t;\n\t"
        "max.f32 tl, tl, 0f00000000;\n\t"
        "max.f32 th, th, 0f00000000;\n\t"
        "mov.b64 t, {tl, th};\n\t"
        "fma.rn.f32x2 %0, t, %3, %0;\n\t"
        "}"
        : "+l"(acc) : "l"(a), "l"(b), "l"(w));
}

// ---------------------------------------------------------------------------
// Init: zero output scalar, seed tp/sp with biases.
// ---------------------------------------------------------------------------
__global__ void init_kernel(const float* __restrict__ bt,
                            const float* __restrict__ bs,
                            float* __restrict__ out, int out_size) {
    int idx = blockIdx.x * blockDim.x + threadIdx.x;
    if (idx < out_size) out[idx] = 0.0f;
    if (idx < BN * HD) {
        int h = idx & (HD - 1);
        g_tp[idx] = bt[h];
        g_sp[idx] = bs[h];
    }
}

// ---------------------------------------------------------------------------
// Projection GEMM: teacher (z=0) / student (z=1), split-K (KLEN=128) with
// atomic accumulate. Block: 32 rows x 128 cols, 256 threads, micro 2x8.
// ---------------------------------------------------------------------------
__global__ void __launch_bounds__(256)
proj_gemm(const float* __restrict__ T, const float* __restrict__ Wt,
          const float* __restrict__ S, const float* __restrict__ Ws) {
    const int KC = 32;
    __shared__ __align__(16) float Xs[32 * KC];       // [r][kk]
    __shared__ __align__(16) float Wsm[KC * HD];      // [kk][c]

    int z = blockIdx.z;
    int ky = blockIdx.y;
    const float* X; const float* W; float* out; int ldx;
    if (z == 0) { X = T; W = Wt; ldx = TD; out = g_tp; }
    else        { if (ky >= SD / 128) return; X = S; W = Ws; ldx = SD; out = g_sp; }

    int tid = threadIdx.x;        // 256
    int tx = tid & 15;            // cols tx*8..+7
    int ty = tid >> 4;            // rows ty*2..+1 (0..15)
    int row0 = blockIdx.x * 32;
    int k0 = ky * 128;

    ull acc[2][4];
#pragma unroll
    for (int m = 0; m < 2; m++)
#pragma unroll
        for (int q = 0; q < 4; q++) acc[m][q] = 0ull;

    for (int kc = 0; kc < 128; kc += KC) {
        // stage X tile 32x32 (256 float4s, one per thread)
        {
            int r = tid >> 3, k4 = (tid & 7) * 4;
            float4 v = *reinterpret_cast<const float4*>(
                &X[(row0 + r) * ldx + k0 + kc + k4]);
            *reinterpret_cast<float4*>(&Xs[r * KC + k4]) = v;
        }
        // stage W tile 32x128 (1024 float4s, 4 per thread)
#pragma unroll
        for (int t = 0; t < 4; t++) {
            int i4 = tid + t * 256;
            int kk = i4 >> 5, c4 = (i4 & 31) * 4;
            float4 v = *reinterpret_cast<const float4*>(
                &W[(k0 + kc + kk) * HD + c4]);
            *reinterpret_cast<float4*>(&Wsm[kk * HD + c4]) = v;
        }
        __syncthreads();
#pragma unroll 8
        for (int kk = 0; kk < KC; kk++) {
            ulonglong2 b01 = *reinterpret_cast<const ulonglong2*>(&Wsm[kk * HD + tx * 8]);
            ulonglong2 b23 = *reinterpret_cast<const ulonglong2*>(&Wsm[kk * HD + tx * 8 + 4]);
#pragma unroll
            for (int m = 0; m < 2; m++) {
                float a = Xs[(ty * 2 + m) * KC + kk];
                ull ad = pk2(a, a);
                fma2(acc[m][0], ad, b01.x);
                fma2(acc[m][1], ad, b01.y);
                fma2(acc[m][2], ad, b23.x);
                fma2(acc[m][3], ad, b23.y);
            }
        }
        __syncthreads();
    }
#pragma unroll
    for (int m = 0; m < 2; m++) {
        int row = row0 + ty * 2 + m;
#pragma unroll
        for (int q = 0; q < 4; q++) {
            float2 v = unpk2(acc[m][q]);
            atomicAdd(&out[row * HD + tx * 8 + q * 2], v.x);
            atomicAdd(&out[row * HD + tx * 8 + q * 2 + 1], v.y);
        }
    }
}

// ---------------------------------------------------------------------------
// U/V projections: [512,128]@[128,128] (+b1 on U). Tile 32 rows x 64 cols,
// 256 threads, micro 2x4. grid (16, 2, 4 mats).
// ---------------------------------------------------------------------------
__global__ void __launch_bounds__(256)
uv_gemm(const float* __restrict__ W1, const float* __restrict__ b1) {
    const int XP = 36;   // Xst stride (pad)
    const int WP = 68;   // Wsm stride (pad)
    __shared__ __align__(16) float Xst[HD * XP];   // [k][r]
    __shared__ __align__(16) float Wsm[32 * WP];   // [kk][c]

    int which = blockIdx.z;
    const float* X = (which < 2) ? g_tp : g_sp;
    const float* W = W1 + ((which & 1) ? HD * HD : 0);
    float* out = (which == 0) ? g_Ut : (which == 1) ? g_Vt
               : (which == 2) ? g_Us : g_Vs;
    bool add_bias = ((which & 1) == 0);

    int tid = threadIdx.x;       // 256
    int tx = tid & 15;           // cols tx*4..+3
    int ty = tid >> 4;           // rows ty*2..+1
    int r0 = blockIdx.x * 32;
    int c0 = blockIdx.y * 64;

    // stage X transposed: 32 rows x 128 K (1024 float4s, 4 per thread)
#pragma unroll
    for (int t = 0; t < 4; t++) {
        int i4 = tid + t * 256;
        int r = i4 >> 5, k4 = (i4 & 31) * 4;
        float4 v = *reinterpret_cast<const float4*>(&X[(r0 + r) * HD + k4]);
        Xst[(k4 + 0) * XP + r] = v.x;
        Xst[(k4 + 1) * XP + r] = v.y;
        Xst[(k4 + 2) * XP + r] = v.z;
        Xst[(k4 + 3) * XP + r] = v.w;
    }

    ull acc[2][2];
#pragma unroll
    for (int m = 0; m < 2; m++) { acc[m][0] = 0ull; acc[m][1] = 0ull; }

    for (int kc = 0; kc < HD; kc += 32) {
        __syncthreads();
        // stage W chunk 32 x 64 (512 float4s, 2 per thread)
#pragma unroll
        for (int t = 0; t < 2; t++) {
            int i4 = tid + t * 256;
            int kk = i4 >> 4, c4 = (i4 & 15) * 4;
            float4 v = *reinterpret_cast<const float4*>(&W[(kc + kk) * HD + c0 + c4]);
            *reinterpret_cast<float4*>(&Wsm[kk * WP + c4]) = v;
        }
        __syncthreads();
#pragma unroll 8
        for (int kk = 0; kk < 32; kk++) {
            int k = kc + kk;
            float2 a2 = *reinterpret_cast<const float2*>(&Xst[k * XP + ty * 2]);
            ulonglong2 bp = *reinterpret_cast<const ulonglong2*>(&Wsm[kk * WP + tx * 4]);
            ull a0 = pk2(a2.x, a2.x), a1 = pk2(a2.y, a2.y);
            fma2(acc[0][0], a0, bp.x); fma2(acc[0][1], a0, bp.y);
            fma2(acc[1][0], a1, bp.x); fma2(acc[1][1], a1, bp.y);
        }
    }

    float4 bias = make_float4(0.f, 0.f, 0.f, 0.f);
    if (add_bias) bias = *reinterpret_cast<const float4*>(&b1[c0 + tx * 4]);
#pragma unroll
    for (int m = 0; m < 2; m++) {
        float2 v0 = unpk2(acc[m][0]);
        float2 v1 = unpk2(acc[m][1]);
        float4 r = make_float4(v0.x + bias.x, v0.y + bias.y,
                               v1.x + bias.z, v1.y + bias.w);
        *reinterpret_cast<float4*>(&out[(r0 + ty * 2 + m) * HD + c0 + tx * 4]) = r;
    }
}

// ---------------------------------------------------------------------------
// Pairwise partial dots. z encodes (net, hsplit): zz = net*4 + half.
// Each block: 32(i) x 64(j) tile, h range [half*32, half*32+32), 128 threads,
// micro 4x4 with f32x2 packing over i-pairs. Writes raw partial sums.
// ---------------------------------------------------------------------------
__global__ void __launch_bounds__(128)
pairwise_part(const float* __restrict__ w2) {
    const int HC = 32;
    const int US = 36;
    const int VS = 68;
    __shared__ __align__(16) float sU[HC * US];   // [h][i-row]
    __shared__ __align__(16) float sV[HC * VS];   // [h][j-row]
    __shared__ __align__(8)  float2 swd[HC];

    int zz = blockIdx.z;         // 0..7
    int net = zz >> 2;
    int hc = (zz & 3) * HC;
    const float* U = net ? g_Us : g_Ut;
    const float* V = net ? g_Vs : g_Vt;
    float* pd = g_pd[zz];

    int tid = threadIdx.x;       // 128
    int tx = tid & 15;           // j = jbase + tx*4 + n
    int ty = tid >> 4;           // i = ibase + ty*4 + m
    int jbase = blockIdx.x * 64;
    int ibase = blockIdx.y * 32;

    // stage U tile (32 h x 32 rows), transposed
#pragma unroll
    for (int t = 0; t < 8; t++) {
        int i = tid + t * 128;           // 1024
        int r = i >> 5, h = i & 31;
        sU[h * US + r] = U[(ibase + r) * HD + hc + h];
    }
    // stage V tile (32 h x 64 rows), transposed
#pragma unroll
    for (int t = 0; t < 16; t++) {
        int i = tid + t * 128;           // 2048
        int r = i >> 5, h = i & 31;
        sV[h * VS + r] = V[(jbase + r) * HD + hc + h];
    }
    if (tid < HC) { float w = w2[hc + tid]; swd[tid] = make_float2(w, w); }
    __syncthreads();

    ull acc[4][2];               // [n][i-pair]
#pragma unroll
    for (int n = 0; n < 4; n++) { acc[n][0] = 0ull; acc[n][1] = 0ull; }

#pragma unroll 8
    for (int h = 0; h < HC; h++) {
        ulonglong2 up = *reinterpret_cast<const ulonglong2*>(&sU[h * US + ty * 4]);
        float4 v4 = *reinterpret_cast<const float4*>(&sV[h * VS + tx * 4]);
        ull wd = *reinterpret_cast<const ull*>(&swd[h]);
        ull vd0 = pk2(v4.x, v4.x);
        ull vd1 = pk2(v4.y, v4.y);
        ull vd2 = pk2(v4.z, v4.z);
        ull vd3 = pk2(v4.w, v4.w);
        rfma2(acc[0][0], up.x, vd0, wd); rfma2(acc[0][1], up.y, vd0, wd);
        rfma2(acc[1][0], up.x, vd1, wd); rfma2(acc[1][1], up.y, vd1, wd);
        rfma2(acc[2][0], up.x, vd2, wd); rfma2(acc[2][1], up.y, vd2, wd);
        rfma2(acc[3][0], up.x, vd3, wd); rfma2(acc[3][1], up.y, vd3, wd);
    }

    // acc[n][p] -> rows: p*2 + {0,1}; store float4 per row
    float sums[4][4];            // [m][n]
#pragma unroll
    for (int n = 0; n < 4; n++) {
#pragma unroll
        for (int p = 0; p < 2; p++) {
            float2 v = unpk2(acc[n][p]);
            sums[p * 2 + 0][n] = v.x;
            sums[p * 2 + 1][n] = v.y;
        }
    }
#pragma unroll
    for (int m = 0; m < 4; m++) {
        int i = ibase + ty * 4 + m;
        *reinterpret_cast<float4*>(&pd[i * BN + jbase + tx * 4]) =
            make_float4(sums[m][0], sums[m][1], sums[m][2], sums[m][3]);
    }
}

// ---------------------------------------------------------------------------
// Reduce: rel = sigmoid(sum of 4 h-partials + b2) per net, diag skipped,
// MSE accumulated into out (zeroed by init).
// ---------------------------------------------------------------------------
__global__ void __launch_bounds__(256)
reduce_kernel(const float* __restrict__ b2v, float* __restrict__ out) {
    __shared__ float sred[256];
    int g = blockIdx.x * 256 + threadIdx.x;     // 65536 groups of 4
    int i = g >> 7;                             // g*4/512
    int j0 = (g & 127) * 4;
    float b2 = b2v[0];

    float4 t = make_float4(0.f, 0.f, 0.f, 0.f);
    float4 s = make_float4(0.f, 0.f, 0.f, 0.f);
#pragma unroll
    for (int k = 0; k < 4; k++) {
        float4 a = *reinterpret_cast<const float4*>(&g_pd[k][g * 4]);
        t.x += a.x; t.y += a.y; t.z += a.z; t.w += a.w;
        float4 b = *reinterpret_cast<const float4*>(&g_pd[4 + k][g * 4]);
        s.x += b.x; s.y += b.y; s.z += b.z; s.w += b.w;
    }
    float tv[4] = {t.x, t.y, t.z, t.w};
    float sv[4] = {s.x, s.y, s.z, s.w};
    float local = 0.0f;
#pragma unroll
    for (int n = 0; n < 4; n++) {
        if (i == j0 + n) continue;   // diagonal: both rel values defined 0
        float rt = 1.0f / (1.0f + __expf(-(tv[n] + b2)));
        float rs = 1.0f / (1.0f + __expf(-(sv[n] + b2)));
        float d = rs - rt;
        local = fmaf(d, d, local);
    }

    sred[threadIdx.x] = local;
    __syncthreads();
    for (int st = 128; st > 0; st >>= 1) {
        if (threadIdx.x < st) sred[threadIdx.x] += sred[threadIdx.x + st];
        __syncthreads();
    }
    if (threadIdx.x == 0)
        atomicAdd(out, sred[0] * (1.0f / ((float)BN * (float)BN)));
}

// ---------------------------------------------------------------------------
extern "C" void kernel_launch(void* const* d_in, const int* in_sizes, int n_in,
                              void* d_out, int out_size) {
    const float* teacher = (const float*)d_in[0];  // [512, 2048]
    const float* student = (const float*)d_in[1];  // [512, 768]
    const float* Wt = (const float*)d_in[2];       // [2048, 128]
    const float* bt = (const float*)d_in[3];       // [128]
    const float* Wsw = (const float*)d_in[4];      // [768, 128]
    const float* bs = (const float*)d_in[5];       // [128]
    const float* W1 = (const float*)d_in[6];       // [256, 128]
    const float* b1 = (const float*)d_in[7];       // [128]
    const float* W2 = (const float*)d_in[8];       // [128, 1]
    const float* b2 = (const float*)d_in[9];       // [1]
    float* out = (float*)d_out;

    init_kernel<<<256, 256>>>(bt, bs, out, out_size);
    proj_gemm<<<dim3(16, 16, 2), 256>>>(teacher, Wt, student, Wsw);
    uv_gemm<<<dim3(16, 2, 4), 256>>>(W1, b1);
    pairwise_part<<<dim3(8, 16, 8), 128>>>(W2);
    reduce_kernel<<<256, 256>>>(b2, out);
}

// round 4
// speedup vs baseline: 1.2872x; 1.2872x over previous
#include <cuda_runtime.h>
#include <math.h>

#define BN 512
#define TD 2048
#define SD 768
#define HD 128

typedef unsigned long long ull;

// Scratch (device globals — no allocations allowed)
__device__ float g_tpp[32][BN*HD];   // teacher proj partials (KLEN=64 -> 32)
__device__ float g_spp[12][BN*HD];   // student proj partials
__device__ float g_tp[BN*HD];
__device__ float g_sp[BN*HD];
// Transposed U/V: [h][row]
__device__ float g_UtT[HD*BN];
__device__ float g_VtT[HD*BN];
__device__ float g_UsT[HD*BN];
__device__ float g_VsT[HD*BN];
// Partial pre-sigmoid dots: [net*4 + hsplit][BN*BN]
__device__ float g_pd[8][BN*BN];

// ---- packed f32x2 helpers (sm_100+) --------------------------------------
__device__ __forceinline__ ull pk2(float a, float b) {
    ull r; asm("mov.b64 %0, {%1, %2};" : "=l"(r) : "f"(a), "f"(b)); return r;
}
__device__ __forceinline__ float2 unpk2(ull v) {
    float2 r; asm("mov.b64 {%0, %1}, %2;" : "=f"(r.x), "=f"(r.y) : "l"(v)); return r;
}
__device__ __forceinline__ void fma2(ull &acc, ull a, ull b) {
    asm("fma.rn.f32x2 %0, %1, %2, %0;" : "+l"(acc) : "l"(a), "l"(b));
}
// acc += relu(a + b) * w (packed 2xfp32)
__device__ __forceinline__ void rfma2(ull &acc, ull a, ull b, ull w) {
    asm("{\n\t"
        ".reg .b64 t;\n\t"
        ".reg .f32 tl, th;\n\t"
        "add.rn.f32x2 t, %1, %2;\n\t"
        "mov.b64 {tl, th}, t;\n\t"
        "max.f32 tl, tl, 0f00000000;\n\t"
        "max.f32 th, th, 0f00000000;\n\t"
        "mov.b64 t, {tl, th};\n\t"
        "fma.rn.f32x2 %0, t, %3, %0;\n\t"
        "}"
        : "+l"(acc) : "l"(a), "l"(b), "l"(w));
}

// ---------------------------------------------------------------------------
// Projection GEMM partials: teacher (z=0, 32 k-splits) / student (z=1, 12).
// KLEN=64. Block: 32 rows x 128 cols, 128 threads, micro 4x8. No atomics.
// ---------------------------------------------------------------------------
__global__ void __launch_bounds__(128)
proj_gemm(const float* __restrict__ T, const float* __restrict__ Wt,
          const float* __restrict__ S, const float* __restrict__ Ws) {
    const int KC = 32;
    __shared__ __align__(16) float Xs[32 * KC];       // [r][kk]
    __shared__ __align__(16) float Wsm[KC * HD];      // [kk][c]

    int z = blockIdx.z;
    int ky = blockIdx.y;
    const float* X; const float* W; float* out; int ldx;
    if (z == 0) { X = T; W = Wt; ldx = TD; out = g_tpp[ky]; }
    else        { if (ky >= 12) return; X = S; W = Ws; ldx = SD; out = g_spp[ky]; }

    int tid = threadIdx.x;        // 128
    int tx = tid & 15;            // cols tx*8..+7
    int ty = tid >> 4;            // rows ty*4..+3
    int row0 = blockIdx.x * 32;
    int k0 = ky * 64;

    ull acc[4][4];
#pragma unroll
    for (int m = 0; m < 4; m++)
#pragma unroll
        for (int q = 0; q < 4; q++) acc[m][q] = 0ull;

#pragma unroll
    for (int kc = 0; kc < 64; kc += KC) {
        // stage X tile 32x32 (256 float4s)
#pragma unroll
        for (int t = 0; t < 2; t++) {
            int i4 = tid + t * 128;
            int r = i4 >> 3, k4 = (i4 & 7) * 4;
            float4 v = *reinterpret_cast<const float4*>(
                &X[(row0 + r) * ldx + k0 + kc + k4]);
            *reinterpret_cast<float4*>(&Xs[r * KC + k4]) = v;
        }
        // stage W tile 32x128 (1024 float4s)
#pragma unroll
        for (int t = 0; t < 8; t++) {
            int i4 = tid + t * 128;
            int kk = i4 >> 5, c4 = (i4 & 31) * 4;
            float4 v = *reinterpret_cast<const float4*>(
                &W[(k0 + kc + kk) * HD + c4]);
            *reinterpret_cast<float4*>(&Wsm[kk * HD + c4]) = v;
        }
        __syncthreads();
#pragma unroll 8
        for (int kk = 0; kk < KC; kk++) {
            ulonglong2 b01 = *reinterpret_cast<const ulonglong2*>(&Wsm[kk * HD + tx * 8]);
            ulonglong2 b23 = *reinterpret_cast<const ulonglong2*>(&Wsm[kk * HD + tx * 8 + 4]);
#pragma unroll
            for (int m = 0; m < 4; m++) {
                float a = Xs[(ty * 4 + m) * KC + kk];
                ull ad = pk2(a, a);
                fma2(acc[m][0], ad, b01.x);
                fma2(acc[m][1], ad, b01.y);
                fma2(acc[m][2], ad, b23.x);
                fma2(acc[m][3], ad, b23.y);
            }
        }
        __syncthreads();
    }
#pragma unroll
    for (int m = 0; m < 4; m++) {
        int row = row0 + ty * 4 + m;
#pragma unroll
        for (int q = 0; q < 2; q++) {
            float2 v0 = unpk2(acc[m][q * 2]);
            float2 v1 = unpk2(acc[m][q * 2 + 1]);
            *reinterpret_cast<float4*>(&out[row * HD + tx * 8 + q * 4]) =
                make_float4(v0.x, v0.y, v1.x, v1.y);
        }
    }
}

// ---------------------------------------------------------------------------
// Sum proj partials + bias -> g_tp / g_sp. Also zeroes the output scalar.
// Grid 128 blocks x 256 thr: blocks 0..63 teacher, 64..127 student.
// ---------------------------------------------------------------------------
__global__ void __launch_bounds__(256)
sumtp(const float* __restrict__ bt, const float* __restrict__ bs,
      float* __restrict__ out, int out_size) {
    if (blockIdx.x == 0) {
        for (int i = threadIdx.x; i < out_size; i += 256) out[i] = 0.0f;
    }
    int b = blockIdx.x;
    int teacher = (b < 64);
    int i4 = (teacher ? b : b - 64) * 256 + threadIdx.x;   // 0..16383 float4
    int k4 = (i4 & 31) * 4;                                // col within HD
    const float* bias = teacher ? bt : bs;
    float4 bv = *reinterpret_cast<const float4*>(&bias[k4]);
    float4 acc = bv;
    int np = teacher ? 32 : 12;
#pragma unroll 4
    for (int p = 0; p < np; p++) {
        const float* src = teacher ? g_tpp[p] : g_spp[p];
        float4 v = *reinterpret_cast<const float4*>(&src[i4 * 4]);
        acc.x += v.x; acc.y += v.y; acc.z += v.z; acc.w += v.w;
    }
    float* dst = teacher ? g_tp : g_sp;
    *reinterpret_cast<float4*>(&dst[i4 * 4]) = acc;
}

// ---------------------------------------------------------------------------
// U/V projections -> TRANSPOSED outputs [h][row].
// Tile 32 rows x 128 cols, 256 threads, micro 4 rows x 4 cols with
// f32x2 packing over ROW pairs. grid (16, 4 mats).
// ---------------------------------------------------------------------------
__global__ void __launch_bounds__(256)
uv_gemm(const float* __restrict__ W1, const float* __restrict__ b1) {
    const int XP = 36;   // Xst stride [k][r]
    const int WP = 132;  // Wsm stride [kk][c]
    __shared__ __align__(16) float Xst[HD * XP];
    __shared__ __align__(16) float Wsm[32 * WP];

    int which = blockIdx.y;
    const float* X = (which < 2) ? g_tp : g_sp;
    const float* W = W1 + ((which & 1) ? HD * HD : 0);
    float* outT = (which == 0) ? g_UtT : (which == 1) ? g_VtT
                : (which == 2) ? g_UsT : g_VsT;
    bool add_bias = ((which & 1) == 0);

    int tid = threadIdx.x;       // 256
    int rowsel = tid & 7;        // rows rowsel*4..+3
    int colsel = tid >> 3;       // cols colsel*4..+3 (0..31 -> 128 cols)
    int r0 = blockIdx.x * 32;

    // stage X transposed [k][r]: 32 rows x 128 K (1024 float4, 4/thread)
#pragma unroll
    for (int t = 0; t < 4; t++) {
        int i4 = tid + t * 256;
        int r = i4 >> 5, k4 = (i4 & 31) * 4;
        float4 v = *reinterpret_cast<const float4*>(&X[(r0 + r) * HD + k4]);
        Xst[(k4 + 0) * XP + r] = v.x;
        Xst[(k4 + 1) * XP + r] = v.y;
        Xst[(k4 + 2) * XP + r] = v.z;
        Xst[(k4 + 3) * XP + r] = v.w;
    }

    ull acc[4][2];   // [col][rowpair]
#pragma unroll
    for (int c = 0; c < 4; c++) { acc[c][0] = 0ull; acc[c][1] = 0ull; }

    for (int kc = 0; kc < HD; kc += 32) {
        __syncthreads();
        // stage W chunk 32 x 128 (1024 float4, 4/thread)
#pragma unroll
        for (int t = 0; t < 4; t++) {
            int i4 = tid + t * 256;
            int kk = i4 >> 5, c4 = (i4 & 31) * 4;
            float4 v = *reinterpret_cast<const float4*>(&W[(kc + kk) * HD + c4]);
            *reinterpret_cast<float4*>(&Wsm[kk * WP + c4]) = v;
        }
        __syncthreads();
#pragma unroll 8
        for (int kk = 0; kk < 32; kk++) {
            int k = kc + kk;
            float2 a01 = *reinterpret_cast<const float2*>(&Xst[k * XP + rowsel * 4]);
            float2 a23 = *reinterpret_cast<const float2*>(&Xst[k * XP + rowsel * 4 + 2]);
            float4 w4 = *reinterpret_cast<const float4*>(&Wsm[kk * WP + colsel * 4]);
            ull ap0 = pk2(a01.x, a01.y), ap1 = pk2(a23.x, a23.y);
            ull w0 = pk2(w4.x, w4.x), w1 = pk2(w4.y, w4.y);
            ull w2d = pk2(w4.z, w4.z), w3 = pk2(w4.w, w4.w);
            fma2(acc[0][0], ap0, w0); fma2(acc[0][1], ap1, w0);
            fma2(acc[1][0], ap0, w1); fma2(acc[1][1], ap1, w1);
            fma2(acc[2][0], ap0, w2d); fma2(acc[2][1], ap1, w2d);
            fma2(acc[3][0], ap0, w3); fma2(acc[3][1], ap1, w3);
        }
    }

    // store transposed: for each col, float4 over 4 consecutive rows
#pragma unroll
    for (int c = 0; c < 4; c++) {
        int col = colsel * 4 + c;
        float bias = add_bias ? b1[col] : 0.0f;
        float2 v0 = unpk2(acc[c][0]);
        float2 v1 = unpk2(acc[c][1]);
        float4 r = make_float4(v0.x + bias, v0.y + bias,
                               v1.x + bias, v1.y + bias);
        *reinterpret_cast<float4*>(&outT[col * BN + r0 + rowsel * 4]) = r;
    }
}

// ---------------------------------------------------------------------------
// Pairwise partial dots. z = net*4 + hsplit. Tile 32(i) x 64(j), 128 thr,
// micro 4x4, f32x2 over i-pairs. Inputs already transposed [h][row].
// ---------------------------------------------------------------------------
__global__ void __launch_bounds__(128)
pairwise_part(const float* __restrict__ w2) {
    const int HC = 32;
    const int US = 36;
    const int VS = 68;
    __shared__ __align__(16) float sU[HC * US];   // [h][i-row]
    __shared__ __align__(16) float sV[HC * VS];   // [h][j-row]
    __shared__ __align__(8)  float2 swd[HC];

    int zz = blockIdx.z;
    int net = zz >> 2;
    int hc = (zz & 3) * HC;
    const float* UT = net ? g_UsT : g_UtT;
    const float* VT = net ? g_VsT : g_VtT;
    float* pd = g_pd[zz];

    int tid = threadIdx.x;       // 128
    int tx = tid & 15;           // j = jbase + tx*4 + n
    int ty = tid >> 4;           // i = ibase + ty*4 + m
    int jbase = blockIdx.x * 64;
    int ibase = blockIdx.y * 32;

    // stage U tile: [h][r], coalesced LDG, conflict-free STS
#pragma unroll
    for (int t = 0; t < 8; t++) {
        int i = tid + t * 128;            // 1024: h = i>>5, r = i&31
        int h = i >> 5, r = i & 31;
        sU[h * US + r] = UT[(hc + h) * BN + ibase + r];
    }
    // stage V tile: 32 h x 64 r
#pragma unroll
    for (int t = 0; t < 16; t++) {
        int i = tid + t * 128;            // 2048: h = i>>6, r = i&63
        int h = i >> 6, r = i & 63;
        sV[h * VS + r] = VT[(hc + h) * BN + jbase + r];
    }
    if (tid < HC) { float w = w2[hc + tid]; swd[tid] = make_float2(w, w); }
    __syncthreads();

    ull acc[4][2];               // [n][i-pair]
#pragma unroll
    for (int n = 0; n < 4; n++) { acc[n][0] = 0ull; acc[n][1] = 0ull; }

#pragma unroll 8
    for (int h = 0; h < HC; h++) {
        ulonglong2 up = *reinterpret_cast<const ulonglong2*>(&sU[h * US + ty * 4]);
        float4 v4 = *reinterpret_cast<const float4*>(&sV[h * VS + tx * 4]);
        ull wd = *reinterpret_cast<const ull*>(&swd[h]);
        ull vd0 = pk2(v4.x, v4.x);
        ull vd1 = pk2(v4.y, v4.y);
        ull vd2 = pk2(v4.z, v4.z);
        ull vd3 = pk2(v4.w, v4.w);
        rfma2(acc[0][0], up.x, vd0, wd); rfma2(acc[0][1], up.y, vd0, wd);
        rfma2(acc[1][0], up.x, vd1, wd); rfma2(acc[1][1], up.y, vd1, wd);
        rfma2(acc[2][0], up.x, vd2, wd); rfma2(acc[2][1], up.y, vd2, wd);
        rfma2(acc[3][0], up.x, vd3, wd); rfma2(acc[3][1], up.y, vd3, wd);
    }

    float sums[4][4];            // [m][n]
#pragma unroll
    for (int n = 0; n < 4; n++) {
#pragma unroll
        for (int p = 0; p < 2; p++) {
            float2 v = unpk2(acc[n][p]);
            sums[p * 2 + 0][n] = v.x;
            sums[p * 2 + 1][n] = v.y;
        }
    }
#pragma unroll
    for (int m = 0; m < 4; m++) {
        int i = ibase + ty * 4 + m;
        *reinterpret_cast<float4*>(&pd[i * BN + jbase + tx * 4]) =
            make_float4(sums[m][0], sums[m][1], sums[m][2], sums[m][3]);
    }
}

// ---------------------------------------------------------------------------
// Reduce: rel = sigmoid(sum of 4 h-partials + b2) per net, diag skipped,
// MSE atomically accumulated into out (zeroed by sumtp).
// ---------------------------------------------------------------------------
__global__ void __launch_bounds__(256)
reduce_kernel(const float* __restrict__ b2v, float* __restrict__ out) {
    __shared__ float sred[256];
    int g = blockIdx.x * 256 + threadIdx.x;     // 65536 groups of 4
    int i = g >> 7;
    int j0 = (g & 127) * 4;
    float b2 = b2v[0];

    float4 t = make_float4(0.f, 0.f, 0.f, 0.f);
    float4 s = make_float4(0.f, 0.f, 0.f, 0.f);
#pragma unroll
    for (int k = 0; k < 4; k++) {
        float4 a = *reinterpret_cast<const float4*>(&g_pd[k][g * 4]);
        t.x += a.x; t.y += a.y; t.z += a.z; t.w += a.w;
        float4 b = *reinterpret_cast<const float4*>(&g_pd[4 + k][g * 4]);
        s.x += b.x; s.y += b.y; s.z += b.z; s.w += b.w;
    }
    float tv[4] = {t.x, t.y, t.z, t.w};
    float sv[4] = {s.x, s.y, s.z, s.w};
    float local = 0.0f;
#pragma unroll
    for (int n = 0; n < 4; n++) {
        if (i == j0 + n) continue;
        float rt = 1.0f / (1.0f + __expf(-(tv[n] + b2)));
        float rs = 1.0f / (1.0f + __expf(-(sv[n] + b2)));
        float d = rs - rt;
        local = fmaf(d, d, local);
    }

    sred[threadIdx.x] = local;
    __syncthreads();
    for (int st = 128; st > 0; st >>= 1) {
        if (threadIdx.x < st) sred[threadIdx.x] += sred[threadIdx.x + st];
        __syncthreads();
    }
    if (threadIdx.x == 0)
        atomicAdd(out, sred[0] * (1.0f / ((float)BN * (float)BN)));
}

// ---------------------------------------------------------------------------
extern "C" void kernel_launch(void* const* d_in, const int* in_sizes, int n_in,
                              void* d_out, int out_size) {
    const float* teacher = (const float*)d_in[0];
    const float* student = (const float*)d_in[1];
    const float* Wt = (const float*)d_in[2];
    const float* bt = (const float*)d_in[3];
    const float* Wsw = (const float*)d_in[4];
    const float* bs = (const float*)d_in[5];
    const float* W1 = (const float*)d_in[6];
    const float* b1 = (const float*)d_in[7];
    const float* W2 = (const float*)d_in[8];
    const float* b2 = (const float*)d_in[9];
    float* out = (float*)d_out;

    proj_gemm<<<dim3(16, 32, 2), 128>>>(teacher, Wt, student, Wsw);
    sumtp<<<128, 256>>>(bt, bs, out, out_size);
    uv_gemm<<<dim3(16, 4), 256>>>(W1, b1);
    pairwise_part<<<dim3(8, 16, 8), 128>>>(W2);
    reduce_kernel<<<256, 256>>>(b2, out);
}